// round 1
// baseline (speedup 1.0000x reference)
#include <cuda_runtime.h>
#include <math.h>

// Problem constants
#define DD   512
#define CCLS 1024
#define BB   4
#define MM   256
#define NN   64

// Device-global scratch (allocation-free per harness rules)
__device__ float g_PE[BB * MM * DD];      // [1024][512]  proj_enc + b1
__device__ float g_PD[BB * NN * DD];      // [256][512]   proj_dec
__device__ float g_W2T[DD * CCLS];        // [512][1024]  W2 transposed (k-major)

// ---------------------------------------------------------------------------
// W2 [1024][512] -> g_W2T [512][1024] tiled transpose
// ---------------------------------------------------------------------------
__global__ void w2_transpose_kernel(const float* __restrict__ W2)
{
    __shared__ float tile[32][33];
    const int k0 = blockIdx.x * 32;   // 512/32 = 16
    const int c0 = blockIdx.y * 32;   // 1024/32 = 32
    const int tx = threadIdx.x;       // 0..31
    const int ty = threadIdx.y;       // 0..7
#pragma unroll
    for (int i = 0; i < 32; i += 8)
        tile[ty + i][tx] = W2[(size_t)(c0 + ty + i) * DD + k0 + tx];
    __syncthreads();
#pragma unroll
    for (int i = 0; i < 32; i += 8)
        g_W2T[(size_t)(k0 + ty + i) * CCLS + c0 + tx] = tile[tx][ty + i];
}

// ---------------------------------------------------------------------------
// Projection GEMM: out[r][k] = (bias) + sum_d X[r][d] * W1[k][off + d]
// W1 row stride = 2*D = 1024. isEnc: out=g_PE, bias=b1, off=0; else g_PD, off=D.
// Tile 64x64, BK=16, 256 threads, 4x4 microtile.
// ---------------------------------------------------------------------------
__global__ __launch_bounds__(256)
void proj_kernel(const float* __restrict__ X, const float* __restrict__ W1,
                 const float* __restrict__ b1, int isEnc)
{
    __shared__ __align__(16) float Xs[16][68];
    __shared__ __align__(16) float Ws[16][68];

    float* outg = isEnc ? g_PE : g_PD;
    const int off = isEnc ? 0 : DD;

    const int r0 = blockIdx.x * 64;
    const int k0 = blockIdx.y * 64;
    const int tid = threadIdx.x;
    const int dd = tid & 15;          // d within slice
    const int rr = tid >> 4;          // 0..15
    const int tx = tid & 15;          // col group
    const int ty = tid >> 4;          // row group

    float acc[4][4];
#pragma unroll
    for (int i = 0; i < 4; ++i)
#pragma unroll
        for (int j = 0; j < 4; ++j) acc[i][j] = 0.f;

    for (int d0 = 0; d0 < DD; d0 += 16) {
#pragma unroll
        for (int i = 0; i < 4; ++i)
            Xs[dd][rr + 16 * i] = X[(size_t)(r0 + rr + 16 * i) * DD + d0 + dd];
#pragma unroll
        for (int i = 0; i < 4; ++i)
            Ws[dd][rr + 16 * i] = W1[(size_t)(k0 + rr + 16 * i) * (2 * DD) + off + d0 + dd];
        __syncthreads();
#pragma unroll
        for (int d = 0; d < 16; ++d) {
            float4 a  = *(const float4*)&Xs[d][ty * 4];
            float4 bv = *(const float4*)&Ws[d][tx * 4];
            float av[4] = {a.x, a.y, a.z, a.w};
            float bw[4] = {bv.x, bv.y, bv.z, bv.w};
#pragma unroll
            for (int i = 0; i < 4; ++i)
#pragma unroll
                for (int j = 0; j < 4; ++j)
                    acc[i][j] = fmaf(av[i], bw[j], acc[i][j]);
        }
        __syncthreads();
    }

#pragma unroll
    for (int i = 0; i < 4; ++i) {
#pragma unroll
        for (int j = 0; j < 4; ++j) {
            float v = acc[i][j];
            if (isEnc) v += b1[k0 + tx * 4 + j];
            outg[(size_t)(r0 + ty * 4 + i) * DD + k0 + tx * 4 + j] = v;
        }
    }
}

// ---------------------------------------------------------------------------
// Fused joint kernel. One CTA = one (b, m) x 32 consecutive n rows.
//   H[n][k] = tanh(PE[bm][k] + PD[b*N + n0 + n][k])   (k-major in SMEM)
//   logits[n][c] = sum_k H[n][k] * W2T[k][c] + b2[c]  (kept in SMEM, full C)
//   out = logits - logsumexp(logits)                  (written once)
// 256 threads; GEMM tile TM=32 x TN=128 x KB=32, 4x4 microtiles, float4 LDS.
// ---------------------------------------------------------------------------
#define HS_STRIDE 36                       // 32 rows + pad (16B aligned, no bank conflicts)
#define W2S_STRIDE 132                     // 128 cols + pad
#define LS_STRIDE 1028                     // 1024 cols + pad
#define JOINT_SMEM_FLOATS (DD * HS_STRIDE + 32 * W2S_STRIDE + 32 * LS_STRIDE)
#define JOINT_SMEM_BYTES (JOINT_SMEM_FLOATS * 4)   // 222208

__global__ __launch_bounds__(256, 1)
void joint_kernel(const float* __restrict__ b2, float* __restrict__ out)
{
    extern __shared__ __align__(16) float smem[];
    float* Hs  = smem;                                   // [512][36]
    float* W2s = smem + DD * HS_STRIDE;                  // [32][132]
    float* Ls  = smem + DD * HS_STRIDE + 32 * W2S_STRIDE; // [32][1028]

    const int tid  = threadIdx.x;
    const int bid  = blockIdx.x;          // 0..2047
    const int half = bid & 1;
    const int bm   = bid >> 1;            // 0..1023  (= b*M + m)
    const int b    = bm >> 8;             // M = 256
    const int n0   = half * 32;

    // ---- Step 1: build H tile (k-major) ----
    const float* PE     = g_PE + (size_t)bm * DD;
    const float* PDbase = g_PD + (size_t)(b * NN + n0) * DD;
    for (int idx = tid; idx < 32 * DD; idx += 256) {
        int n = idx >> 9;                 // 0..31
        int k = idx & (DD - 1);           // 0..511
        Hs[k * HS_STRIDE + n] = tanhf(PE[k] + PDbase[(size_t)n * DD + k]);
    }
    __syncthreads();

    const int ct = tid & 31;              // col thread: cols ct*4 .. ct*4+3
    const int rt = tid >> 5;              // row thread: rows rt*4 .. rt*4+3 (rt 0..7)

    // ---- Step 2: GEMM into Ls, 8 chunks of TN=128 over C=1024 ----
    for (int cc = 0; cc < 8; ++cc) {
        const int c0 = cc * 128;
        float acc[4][4];
#pragma unroll
        for (int i = 0; i < 4; ++i)
#pragma unroll
            for (int j = 0; j < 4; ++j) acc[i][j] = 0.f;

        for (int kb = 0; kb < 16; ++kb) {
            // Stage W2T slice [32 k][128 c] -> W2s (coalesced, conflict-free, float4)
#pragma unroll
            for (int l = 0; l < 4; ++l) {
                int idx = tid + l * 256;          // 0..1023 float4s
                int k   = idx >> 5;               // 0..31
                int c4  = idx & 31;               // 0..31
                *(float4*)&W2s[k * W2S_STRIDE + c4 * 4] =
                    *(const float4*)&g_W2T[(size_t)(kb * 32 + k) * CCLS + c0 + c4 * 4];
            }
            __syncthreads();

            const float* hb = Hs + kb * 32 * HS_STRIDE;
#pragma unroll
            for (int k = 0; k < 32; ++k) {
                float4 a  = *(const float4*)&hb[k * HS_STRIDE + rt * 4];
                float4 bv = *(const float4*)&W2s[k * W2S_STRIDE + ct * 4];
                float av[4] = {a.x, a.y, a.z, a.w};
                float bw[4] = {bv.x, bv.y, bv.z, bv.w};
#pragma unroll
                for (int i = 0; i < 4; ++i)
#pragma unroll
                    for (int j = 0; j < 4; ++j)
                        acc[i][j] = fmaf(av[i], bw[j], acc[i][j]);
            }
            __syncthreads();
        }

        // + b2, store chunk to Ls (float4)
        float4 bb = *(const float4*)&b2[c0 + ct * 4];
        float bbv[4] = {bb.x, bb.y, bb.z, bb.w};
#pragma unroll
        for (int i = 0; i < 4; ++i) {
            float4 v;
            v.x = acc[i][0] + bbv[0];
            v.y = acc[i][1] + bbv[1];
            v.z = acc[i][2] + bbv[2];
            v.w = acc[i][3] + bbv[3];
            *(float4*)&Ls[(rt * 4 + i) * LS_STRIDE + c0 + ct * 4] = v;
        }
    }
    __syncthreads();

    // ---- Step 3: log-softmax per row, write output once ----
    const int warp = tid >> 5, lane = tid & 31;
    for (int r = warp; r < 32; r += 8) {
        const float* row = Ls + r * LS_STRIDE;
        float mx = -INFINITY;
#pragma unroll
        for (int c = lane; c < CCLS; c += 32) mx = fmaxf(mx, row[c]);
#pragma unroll
        for (int o = 16; o; o >>= 1) mx = fmaxf(mx, __shfl_xor_sync(0xffffffffu, mx, o));
        float s = 0.f;
#pragma unroll
        for (int c = lane; c < CCLS; c += 32) s += __expf(row[c] - mx);
#pragma unroll
        for (int o = 16; o; o >>= 1) s += __shfl_xor_sync(0xffffffffu, s, o);
        float lse = mx + logf(s);

        float* orow = out + (size_t)(bm * NN + n0 + r) * CCLS;
#pragma unroll
        for (int c = lane; c < CCLS; c += 32) orow[c] = row[c] - lse;
    }
}

// ---------------------------------------------------------------------------
// Launch
// ---------------------------------------------------------------------------
extern "C" void kernel_launch(void* const* d_in, const int* in_sizes, int n_in,
                              void* d_out, int out_size)
{
    const float* enc = (const float*)d_in[0];   // [4,256,512]
    const float* dec = (const float*)d_in[1];   // [4,64,512]
    const float* W1  = (const float*)d_in[2];   // [512,1024]
    const float* b1  = (const float*)d_in[3];   // [512]
    const float* W2  = (const float*)d_in[4];   // [1024,512]
    const float* b2  = (const float*)d_in[5];   // [1024]
    float* out = (float*)d_out;                 // [4,256,64,1024] fp32

    // Idempotent; ignore return (first non-captured correctness call sets it).
    cudaFuncSetAttribute(joint_kernel,
                         cudaFuncAttributeMaxDynamicSharedMemorySize,
                         JOINT_SMEM_BYTES);

    w2_transpose_kernel<<<dim3(16, 32), dim3(32, 8)>>>(W2);
    proj_kernel<<<dim3(16, 8), 256>>>(enc, W1, b1, 1);   // -> g_PE (+b1)
    proj_kernel<<<dim3(4, 8), 256>>>(dec, W1, b1, 0);    // -> g_PD
    joint_kernel<<<2048, 256, JOINT_SMEM_BYTES>>>(b2, out);
}

// round 10
// speedup vs baseline: 4.5986x; 4.5986x over previous
#include <cuda_runtime.h>
#include <cuda_bf16.h>
#include <math.h>
#include <stdint.h>

// Problem constants
#define DD   512
#define CCLS 1024
#define BB   4
#define MM   256
#define NN   64
#define RR_TOT (BB * MM * NN)   // 65536 rows

// Device-global scratch (allocation-free per harness rules)
__device__ float g_PE[BB * MM * DD];            // [1024][512]  proj_enc + b1
__device__ float g_PD[BB * NN * DD];            // [256][512]   proj_dec
__device__ __nv_bfloat16 g_W2b[CCLS * DD];      // [1024][512]  W2 in bf16 (k-major)
__device__ __nv_bfloat16 g_Hb[(size_t)RR_TOT * DD]; // [65536][512] tanh hidden, bf16

__device__ __forceinline__ uint32_t smem_to_u32(const void* p) {
    uint32_t a;
    asm("{ .reg .u64 t; cvta.to.shared.u64 t, %1; cvt.u32.u64 %0, t; }" : "=r"(a) : "l"(p));
    return a;
}

// ---------------------------------------------------------------------------
// W2 fp32 -> bf16
// ---------------------------------------------------------------------------
__global__ void w2_to_bf16_kernel(const float* __restrict__ W2)
{
    int i = blockIdx.x * 256 + threadIdx.x;   // grid 2048 covers 524288
    g_W2b[i] = __float2bfloat16(W2[i]);
}

// ---------------------------------------------------------------------------
// Projection GEMM (fp32 CUDA cores, small): out[r][k] = (b1) + X[r]·W1[k][off:]
// ---------------------------------------------------------------------------
__global__ __launch_bounds__(256)
void proj_kernel(const float* __restrict__ X, const float* __restrict__ W1,
                 const float* __restrict__ b1, int isEnc)
{
    __shared__ __align__(16) float Xs[16][68];
    __shared__ __align__(16) float Ws[16][68];

    float* outg = isEnc ? g_PE : g_PD;
    const int off = isEnc ? 0 : DD;

    const int r0 = blockIdx.x * 64;
    const int k0 = blockIdx.y * 64;
    const int tid = threadIdx.x;
    const int dd = tid & 15;
    const int rr = tid >> 4;
    const int tx = tid & 15;
    const int ty = tid >> 4;

    float acc[4][4];
#pragma unroll
    for (int i = 0; i < 4; ++i)
#pragma unroll
        for (int j = 0; j < 4; ++j) acc[i][j] = 0.f;

    for (int d0 = 0; d0 < DD; d0 += 16) {
#pragma unroll
        for (int i = 0; i < 4; ++i)
            Xs[dd][rr + 16 * i] = X[(size_t)(r0 + rr + 16 * i) * DD + d0 + dd];
#pragma unroll
        for (int i = 0; i < 4; ++i)
            Ws[dd][rr + 16 * i] = W1[(size_t)(k0 + rr + 16 * i) * (2 * DD) + off + d0 + dd];
        __syncthreads();
#pragma unroll
        for (int d = 0; d < 16; ++d) {
            float4 a  = *(const float4*)&Xs[d][ty * 4];
            float4 bv = *(const float4*)&Ws[d][tx * 4];
            float av[4] = {a.x, a.y, a.z, a.w};
            float bw[4] = {bv.x, bv.y, bv.z, bv.w};
#pragma unroll
            for (int i = 0; i < 4; ++i)
#pragma unroll
                for (int j = 0; j < 4; ++j)
                    acc[i][j] = fmaf(av[i], bw[j], acc[i][j]);
        }
        __syncthreads();
    }
#pragma unroll
    for (int i = 0; i < 4; ++i)
#pragma unroll
        for (int j = 0; j < 4; ++j) {
            float v = acc[i][j];
            if (isEnc) v += b1[k0 + tx * 4 + j];
            outg[(size_t)(r0 + ty * 4 + i) * DD + k0 + tx * 4 + j] = v;
        }
}

// ---------------------------------------------------------------------------
// H build: g_Hb[bm*64+n][k] = bf16(tanh(PE[bm][k] + PD[b*64+n][k]))
// ---------------------------------------------------------------------------
__global__ __launch_bounds__(256)
void h_build_kernel()
{
    const int bm = blockIdx.x;
    const int b  = bm >> 8;
    const float* PE = g_PE + (size_t)bm * DD;
    const float* PD = g_PD + (size_t)(b * NN) * DD;
    __nv_bfloat16* H = g_Hb + (size_t)bm * NN * DD;

    for (int i = threadIdx.x; i < NN * (DD / 2); i += 256) {
        int n  = i >> 8;            // 0..63
        int kp = i & 255;           // pair index
        int k  = kp * 2;
        float2 pe = *(const float2*)(PE + k);
        float2 pd = *(const float2*)(PD + (size_t)n * DD + k);
        float t0, t1;
        asm("tanh.approx.f32 %0, %1;" : "=f"(t0) : "f"(pe.x + pd.x));
        asm("tanh.approx.f32 %0, %1;" : "=f"(t1) : "f"(pe.y + pd.y));
        *(__nv_bfloat162*)(H + (size_t)n * DD + k) = __floats2bfloat162_rn(t0, t1);
    }
}

// ---------------------------------------------------------------------------
// Fused joint GEMM via mma.sync (HMMA bf16) + bias + log-softmax
// Grid 512 x 256 threads (8 warps). CTA: rows [r0, r0+128), C=1024 in 8 chunks
// of 128 cols. Warp (rg, cg): rg=wid>>1 rows [rg*32,+32), cg=wid&1 cols
// [cg*64,+64) of the chunk. K=512 as 8 slices of 64 (double-buffered smem B).
// ---------------------------------------------------------------------------
#define A_STRIDE 1040                  // bytes per A row (520 bf16): LDSM conflict-free
#define B_STRIDE 144                   // bytes per B row (72 bf16)
#define B_SLICE  (128 * B_STRIDE)      // 18432
#define A_OFF    0                     // 128*1040 = 133120
#define B_OFF    133120                // 2 slices = 36864
#define B2_OFF   169984                // 4096
#define SCR_OFF  174080                // float2[128][2] = 2048
#define LSE_OFF  176128                // 512
#define GEMM_SMEM 176640

__device__ __forceinline__ void ldsm_x4(uint32_t& a0, uint32_t& a1, uint32_t& a2, uint32_t& a3,
                                        uint32_t addr) {
    asm volatile("ldmatrix.sync.aligned.m8n8.x4.shared.b16 {%0,%1,%2,%3}, [%4];"
                 : "=r"(a0), "=r"(a1), "=r"(a2), "=r"(a3) : "r"(addr));
}
__device__ __forceinline__ void ldsm_x2(uint32_t& b0, uint32_t& b1, uint32_t addr) {
    asm volatile("ldmatrix.sync.aligned.m8n8.x2.shared.b16 {%0,%1}, [%2];"
                 : "=r"(b0), "=r"(b1) : "r"(addr));
}
__device__ __forceinline__ void mma16816(float* d, uint32_t a0, uint32_t a1, uint32_t a2,
                                         uint32_t a3, uint32_t b0, uint32_t b1) {
    asm volatile("mma.sync.aligned.m16n8k16.row.col.f32.bf16.bf16.f32 "
                 "{%0,%1,%2,%3}, {%4,%5,%6,%7}, {%8,%9}, {%0,%1,%2,%3};"
                 : "+f"(d[0]), "+f"(d[1]), "+f"(d[2]), "+f"(d[3])
                 : "r"(a0), "r"(a1), "r"(a2), "r"(a3), "r"(b0), "r"(b1));
}

__global__ __launch_bounds__(256, 1)
void gemm_joint_kernel(const float* __restrict__ b2, float* __restrict__ out)
{
    extern __shared__ __align__(16) char smem[];
    const uint32_t sb = smem_to_u32(smem);
    const int tid  = threadIdx.x;
    const int wid  = tid >> 5;
    const int lane = tid & 31;
    const int rg   = wid >> 1;            // row group 0..3
    const int cg   = wid & 1;             // col group 0..1
    const int r0   = blockIdx.x * 128;

    float* b2s = (float*)(smem + B2_OFF);
    float2* scr = (float2*)(smem + SCR_OFF);   // [row][colg]
    float* lse = (float*)(smem + LSE_OFF);

    // b2 -> smem
    for (int i = tid; i < CCLS; i += 256) b2s[i] = b2[i];

    // Stage A tile: 128 rows x 512 bf16, padded stride
    {
        const __nv_bfloat16* Hbase = g_Hb + (size_t)r0 * DD;
        for (int idx = tid; idx < 128 * 64; idx += 256) {
            int row = idx >> 6;
            int kc  = idx & 63;
            uint4 v = *(const uint4*)(Hbase + (size_t)row * DD + kc * 8);
            *(uint4*)(smem + A_OFF + row * A_STRIDE + kc * 16) = v;
        }
    }

    // ldmatrix lane address components
    const uint32_t aLane = sb + A_OFF + (rg * 32 + (lane & 15)) * A_STRIDE + (lane >> 4) * 16;
    const uint32_t bLaneBase = sb + B_OFF +
        (cg * 64 + (lane & 7)) * B_STRIDE + ((lane >> 3) & 1) * 16;

    // B prefetch: thread loads 4 uint4 per slice
    const int pn = tid >> 3;        // 0..31  (n row handled: pn + j*32)
    const int pk = tid & 7;         // 16B chunk within 128B slice row
    uint4 pb[4];
#pragma unroll
    for (int j = 0; j < 4; ++j)
        pb[j] = *(const uint4*)(g_W2b + (size_t)(pn + j * 32) * DD + pk * 8);  // chunk0,kb0

    float mr[4], sr[4];
#pragma unroll
    for (int i = 0; i < 4; ++i) { mr[i] = -INFINITY; sr[i] = 0.f; }

    for (int chunk = 0; chunk < 8; ++chunk) {
        float acc[16][4];                 // [t*8+nt][4]
#pragma unroll
        for (int i = 0; i < 16; ++i)
#pragma unroll
            for (int j = 0; j < 4; ++j) acc[i][j] = 0.f;

        for (int kb = 0; kb < 8; ++kb) {
            const int stage = chunk * 8 + kb;
            const int buf = stage & 1;
            // store prefetched slice
            char* bd = smem + B_OFF + buf * B_SLICE;
#pragma unroll
            for (int j = 0; j < 4; ++j)
                *(uint4*)(bd + (pn + j * 32) * B_STRIDE + pk * 16) = pb[j];
            __syncthreads();

            // prefetch next slice
            if (stage < 63) {
                const int ns = stage + 1;
                const int nc = ns >> 3, nkb = ns & 7;
                const __nv_bfloat16* src =
                    g_W2b + (size_t)(nc * 128 + pn) * DD + nkb * 64 + pk * 8;
#pragma unroll
                for (int j = 0; j < 4; ++j)
                    pb[j] = *(const uint4*)(src + (size_t)j * 32 * DD);
            }

            // compute: 4 k-steps of 16 over this 64-k slice
            const uint32_t bSlice = bLaneBase + buf * B_SLICE;
#pragma unroll
            for (int ks = 0; ks < 4; ++ks) {
                uint32_t a0[2], a1[2], a2[2], a3[2];
#pragma unroll
                for (int t = 0; t < 2; ++t)
                    ldsm_x4(a0[t], a1[t], a2[t], a3[t],
                            aLane + t * 16 * A_STRIDE + (kb * 64 + ks * 16) * 2);
#pragma unroll
                for (int nt = 0; nt < 8; ++nt) {
                    uint32_t b0, b1;
                    ldsm_x2(b0, b1, bSlice + nt * 8 * B_STRIDE + ks * 32);
                    mma16816(acc[nt],     a0[0], a1[0], a2[0], a3[0], b0, b1);
                    mma16816(acc[8 + nt], a0[1], a1[1], a2[1], a3[1], b0, b1);
                }
            }
            __syncthreads();
        }

        // ---- chunk epilogue: +b2, online lse, store raw logits ----
        const int cbase = chunk * 128 + cg * 64 + (lane & 3) * 2;
#pragma unroll
        for (int t = 0; t < 2; ++t) {
#pragma unroll
            for (int h = 0; h < 2; ++h) {
                const int idx = t * 2 + h;
                const int row = r0 + rg * 32 + (lane >> 2) + t * 16 + h * 8;
                float x[16];
#pragma unroll
                for (int nt = 0; nt < 8; ++nt) {
                    float2 bv = *(const float2*)&b2s[cbase + nt * 8];
                    x[nt * 2]     = acc[t * 8 + nt][h * 2]     + bv.x;
                    x[nt * 2 + 1] = acc[t * 8 + nt][h * 2 + 1] + bv.y;
                }
                float mx = x[0];
#pragma unroll
                for (int i = 1; i < 16; ++i) mx = fmaxf(mx, x[i]);
                float nm = fmaxf(mr[idx], mx);
                float part = 0.f;
#pragma unroll
                for (int i = 0; i < 16; ++i) part += __expf(x[i] - nm);
                sr[idx] = sr[idx] * __expf(mr[idx] - nm) + part;
                mr[idx] = nm;

                float* orow = out + (size_t)row * CCLS + cbase;
#pragma unroll
                for (int nt = 0; nt < 8; ++nt)
                    *(float2*)(orow + nt * 8) = make_float2(x[nt * 2], x[nt * 2 + 1]);
            }
        }
    }

    // ---- combine lse across lanes (cols within warp), then across col groups ----
#pragma unroll
    for (int idx = 0; idx < 4; ++idx) {
        float m = mr[idx], s = sr[idx];
#pragma unroll
        for (int off = 1; off <= 2; off <<= 1) {
            float om = __shfl_xor_sync(0xffffffffu, m, off);
            float os = __shfl_xor_sync(0xffffffffu, s, off);
            float nm = fmaxf(m, om);
            s = s * __expf(m - nm) + os * __expf(om - nm);
            m = nm;
        }
        if ((lane & 3) == 0) {
            const int t = idx >> 1, h = idx & 1;
            const int row = rg * 32 + (lane >> 2) + t * 16 + h * 8;
            scr[row * 2 + cg] = make_float2(m, s);
        }
    }
    __syncthreads();

    if (tid < 128) {
        float2 p = scr[tid * 2 + 0];
        float2 q = scr[tid * 2 + 1];
        float nm = fmaxf(p.x, q.x);
        float s = p.y * __expf(p.x - nm) + q.y * __expf(q.x - nm);
        lse[tid] = nm + logf(s);
    }
    __syncthreads();

    // ---- fixup: subtract lse over this CTA's 128x1024 block (L2-hot) ----
    for (int idx = tid; idx < 128 * 256; idx += 256) {
        int row = idx >> 8;
        int c4  = (idx & 255) * 4;
        float* p = out + (size_t)(r0 + row) * CCLS + c4;
        float4 v = *(const float4*)p;
        float l = lse[row];
        v.x -= l; v.y -= l; v.z -= l; v.w -= l;
        *(float4*)p = v;
    }
}

// ---------------------------------------------------------------------------
// Launch
// ---------------------------------------------------------------------------
extern "C" void kernel_launch(void* const* d_in, const int* in_sizes, int n_in,
                              void* d_out, int out_size)
{
    const float* enc = (const float*)d_in[0];   // [4,256,512]
    const float* dec = (const float*)d_in[1];   // [4,64,512]
    const float* W1  = (const float*)d_in[2];   // [512,1024]
    const float* b1  = (const float*)d_in[3];   // [512]
    const float* W2  = (const float*)d_in[4];   // [1024,512]
    const float* b2  = (const float*)d_in[5];   // [1024]
    float* out = (float*)d_out;                 // [4,256,64,1024] fp32

    cudaFuncSetAttribute(gemm_joint_kernel,
                         cudaFuncAttributeMaxDynamicSharedMemorySize, GEMM_SMEM);

    w2_to_bf16_kernel<<<2048, 256>>>(W2);
    proj_kernel<<<dim3(16, 8), 256>>>(enc, W1, b1, 1);   // -> g_PE (+b1)
    proj_kernel<<<dim3(4, 8), 256>>>(dec, W1, b1, 0);    // -> g_PD
    h_build_kernel<<<1024, 256>>>();                     // -> g_Hb (bf16)
    gemm_joint_kernel<<<512, 256, GEMM_SMEM>>>(b2, out);
}

// round 12
// speedup vs baseline: 5.2317x; 1.1377x over previous
#include <cuda_runtime.h>
#include <cuda_bf16.h>
#include <math.h>
#include <stdint.h>

// Problem constants
#define DD   512
#define CCLS 1024
#define BB   4
#define MM   256
#define NN   64
#define RR_TOT (BB * MM * NN)   // 65536 rows

// Device-global scratch (allocation-free per harness rules)
__device__ float g_PE[BB * MM * DD];            // [1024][512]  proj_enc + b1
__device__ float g_PD[BB * NN * DD];            // [256][512]   proj_dec
__device__ __nv_bfloat16 g_W2b[CCLS * DD];      // [1024][512]  W2 in bf16 (k-major)
__device__ __nv_bfloat16 g_Hb[(size_t)RR_TOT * DD]; // [65536][512] tanh hidden, bf16

__device__ __forceinline__ uint32_t smem_to_u32(const void* p) {
    uint32_t a;
    asm("{ .reg .u64 t; cvta.to.shared.u64 t, %1; cvt.u32.u64 %0, t; }" : "=r"(a) : "l"(p));
    return a;
}

// ---------------------------------------------------------------------------
// W2 fp32 -> bf16
// ---------------------------------------------------------------------------
__global__ void w2_to_bf16_kernel(const float* __restrict__ W2)
{
    int i = blockIdx.x * 256 + threadIdx.x;   // grid 2048 covers 524288
    g_W2b[i] = __float2bfloat16(W2[i]);
}

// ---------------------------------------------------------------------------
// Projection GEMM (fp32 CUDA cores, small): out[r][k] = (b1) + X[r]·W1[k][off:]
// ---------------------------------------------------------------------------
__global__ __launch_bounds__(256)
void proj_kernel(const float* __restrict__ X, const float* __restrict__ W1,
                 const float* __restrict__ b1, int isEnc)
{
    __shared__ __align__(16) float Xs[16][68];
    __shared__ __align__(16) float Ws[16][68];

    float* outg = isEnc ? g_PE : g_PD;
    const int off = isEnc ? 0 : DD;

    const int r0 = blockIdx.x * 64;
    const int k0 = blockIdx.y * 64;
    const int tid = threadIdx.x;
    const int dd = tid & 15;
    const int rr = tid >> 4;
    const int tx = tid & 15;
    const int ty = tid >> 4;

    float acc[4][4];
#pragma unroll
    for (int i = 0; i < 4; ++i)
#pragma unroll
        for (int j = 0; j < 4; ++j) acc[i][j] = 0.f;

    for (int d0 = 0; d0 < DD; d0 += 16) {
#pragma unroll
        for (int i = 0; i < 4; ++i)
            Xs[dd][rr + 16 * i] = X[(size_t)(r0 + rr + 16 * i) * DD + d0 + dd];
#pragma unroll
        for (int i = 0; i < 4; ++i)
            Ws[dd][rr + 16 * i] = W1[(size_t)(k0 + rr + 16 * i) * (2 * DD) + off + d0 + dd];
        __syncthreads();
#pragma unroll
        for (int d = 0; d < 16; ++d) {
            float4 a  = *(const float4*)&Xs[d][ty * 4];
            float4 bv = *(const float4*)&Ws[d][tx * 4];
            float av[4] = {a.x, a.y, a.z, a.w};
            float bw[4] = {bv.x, bv.y, bv.z, bv.w};
#pragma unroll
            for (int i = 0; i < 4; ++i)
#pragma unroll
                for (int j = 0; j < 4; ++j)
                    acc[i][j] = fmaf(av[i], bw[j], acc[i][j]);
        }
        __syncthreads();
    }
#pragma unroll
    for (int i = 0; i < 4; ++i)
#pragma unroll
        for (int j = 0; j < 4; ++j) {
            float v = acc[i][j];
            if (isEnc) v += b1[k0 + tx * 4 + j];
            outg[(size_t)(r0 + ty * 4 + i) * DD + k0 + tx * 4 + j] = v;
        }
}

// ---------------------------------------------------------------------------
// H build (vectorized): g_Hb[bm*64+n][k] = bf16(tanh(PE[bm][k] + PD[b*64+n][k]))
// ---------------------------------------------------------------------------
__global__ __launch_bounds__(256)
void h_build_kernel()
{
    const int bm = blockIdx.x;
    const int b  = bm >> 8;
    const float* PE = g_PE + (size_t)bm * DD;
    const float* PD = g_PD + (size_t)(b * NN) * DD;
    __nv_bfloat16* H = g_Hb + (size_t)bm * NN * DD;

    for (int i = threadIdx.x; i < NN * (DD / 4); i += 256) {
        int n  = i >> 7;            // 0..63
        int kq = i & 127;           // quad index
        int k  = kq * 4;
        float4 pe = *(const float4*)(PE + k);
        float4 pd = *(const float4*)(PD + (size_t)n * DD + k);
        float t0, t1, t2, t3;
        asm("tanh.approx.f32 %0, %1;" : "=f"(t0) : "f"(pe.x + pd.x));
        asm("tanh.approx.f32 %0, %1;" : "=f"(t1) : "f"(pe.y + pd.y));
        asm("tanh.approx.f32 %0, %1;" : "=f"(t2) : "f"(pe.z + pd.z));
        asm("tanh.approx.f32 %0, %1;" : "=f"(t3) : "f"(pe.w + pd.w));
        __nv_bfloat162 b0 = __floats2bfloat162_rn(t0, t1);
        __nv_bfloat162 b1v = __floats2bfloat162_rn(t2, t3);
        uint2 pack;
        pack.x = *(uint32_t*)&b0;
        pack.y = *(uint32_t*)&b1v;
        *(uint2*)(H + (size_t)n * DD + k) = pack;
    }
}

// ---------------------------------------------------------------------------
// Fused joint GEMM via mma.sync (HMMA bf16) + bias + log-softmax
// Grid 512 x 512 threads (16 warps: 4 rg x 4 cg). CTA: rows [r0, r0+128),
// C=1024 in 8 chunks of 128 cols; warp covers rows [rg*32,+32) x cols
// [cg*32,+32) of the chunk. K=512 as 4 slices of 128 (double-buffered B).
// ---------------------------------------------------------------------------
#define A_STRIDE 1040                  // bytes per A row (520 bf16)
#define B_STRIDE 272                   // bytes per B row (136 bf16)
#define B_SLICE  (128 * B_STRIDE)      // 34816
#define A_OFF    0                     // 128*1040 = 133120
#define B_OFF    133120                // 2 slices = 69632
#define B2_OFF   202752                // 4096
#define SCR_OFF  206848                // float2[128][4] = 4096
#define LSE_OFF  210944                // 512
#define GEMM_SMEM 211456

__device__ __forceinline__ void ldsm_x4(uint32_t& a0, uint32_t& a1, uint32_t& a2, uint32_t& a3,
                                        uint32_t addr) {
    asm volatile("ldmatrix.sync.aligned.m8n8.x4.shared.b16 {%0,%1,%2,%3}, [%4];"
                 : "=r"(a0), "=r"(a1), "=r"(a2), "=r"(a3) : "r"(addr));
}
__device__ __forceinline__ void ldsm_x2(uint32_t& b0, uint32_t& b1, uint32_t addr) {
    asm volatile("ldmatrix.sync.aligned.m8n8.x2.shared.b16 {%0,%1}, [%2];"
                 : "=r"(b0), "=r"(b1) : "r"(addr));
}
__device__ __forceinline__ void mma16816(float* d, uint32_t a0, uint32_t a1, uint32_t a2,
                                         uint32_t a3, uint32_t b0, uint32_t b1) {
    asm volatile("mma.sync.aligned.m16n8k16.row.col.f32.bf16.bf16.f32 "
                 "{%0,%1,%2,%3}, {%4,%5,%6,%7}, {%8,%9}, {%0,%1,%2,%3};"
                 : "+f"(d[0]), "+f"(d[1]), "+f"(d[2]), "+f"(d[3])
                 : "r"(a0), "r"(a1), "r"(a2), "r"(a3), "r"(b0), "r"(b1));
}

__global__ __launch_bounds__(512, 1)
void gemm_joint_kernel(const float* __restrict__ b2, float* __restrict__ out)
{
    extern __shared__ __align__(16) char smem[];
    const uint32_t sb = smem_to_u32(smem);
    const int tid  = threadIdx.x;
    const int wid  = tid >> 5;
    const int lane = tid & 31;
    const int rg   = wid >> 2;            // row group 0..3
    const int cg   = wid & 3;             // col group 0..3
    const int r0   = blockIdx.x * 128;

    float* b2s = (float*)(smem + B2_OFF);
    float2* scr = (float2*)(smem + SCR_OFF);   // [row][colg 0..3]
    float* lse = (float*)(smem + LSE_OFF);

    // b2 -> smem
    for (int i = tid; i < CCLS; i += 512) b2s[i] = b2[i];

    // Stage A tile: 128 rows x 512 bf16, padded stride
    {
        const __nv_bfloat16* Hbase = g_Hb + (size_t)r0 * DD;
        for (int idx = tid; idx < 128 * 64; idx += 512) {
            int row = idx >> 6;
            int kc  = idx & 63;
            uint4 v = *(const uint4*)(Hbase + (size_t)row * DD + kc * 8);
            *(uint4*)(smem + A_OFF + row * A_STRIDE + kc * 16) = v;
        }
    }

    // ldmatrix lane addresses
    const uint32_t aLane = sb + A_OFF + (rg * 32 + (lane & 15)) * A_STRIDE + (lane >> 4) * 16;
    const uint32_t bLaneBase = sb + B_OFF +
        (cg * 32 + (lane & 7)) * B_STRIDE + ((lane >> 3) & 1) * 16;

    // B prefetch: thread loads 4 uint4 per 128x128k slice (32KB / 512 thr)
    const int pn = tid >> 4;        // 0..31  (rows pn + j*32)
    const int pk = tid & 15;        // 16B chunk within 256B slice row
    uint4 pb[4];
#pragma unroll
    for (int j = 0; j < 4; ++j)
        pb[j] = *(const uint4*)(g_W2b + (size_t)(pn + j * 32) * DD + pk * 8);  // chunk0,slice0

    float mr[4], sr[4];
#pragma unroll
    for (int i = 0; i < 4; ++i) { mr[i] = -INFINITY; sr[i] = 0.f; }

    for (int chunk = 0; chunk < 8; ++chunk) {
        float acc[8][4];                  // [t*4+nt][4]
#pragma unroll
        for (int i = 0; i < 8; ++i)
#pragma unroll
            for (int j = 0; j < 4; ++j) acc[i][j] = 0.f;

        for (int kb = 0; kb < 4; ++kb) {
            const int stage = chunk * 4 + kb;
            const int buf = stage & 1;
            // store prefetched slice
            char* bd = smem + B_OFF + buf * B_SLICE;
#pragma unroll
            for (int j = 0; j < 4; ++j)
                *(uint4*)(bd + (pn + j * 32) * B_STRIDE + pk * 16) = pb[j];
            __syncthreads();

            // prefetch next slice
            if (stage < 31) {
                const int ns = stage + 1;
                const int nc = ns >> 2, nkb = ns & 3;
                const __nv_bfloat16* src =
                    g_W2b + (size_t)(nc * 128 + pn) * DD + nkb * 128 + pk * 8;
#pragma unroll
                for (int j = 0; j < 4; ++j)
                    pb[j] = *(const uint4*)(src + (size_t)j * 32 * DD);
            }

            // compute: 8 k-steps of 16 over this 128-k slice
            const uint32_t bSlice = bLaneBase + buf * B_SLICE;
#pragma unroll
            for (int ks = 0; ks < 8; ++ks) {
                uint32_t a0[2], a1[2], a2[2], a3[2];
#pragma unroll
                for (int t = 0; t < 2; ++t)
                    ldsm_x4(a0[t], a1[t], a2[t], a3[t],
                            aLane + t * 16 * A_STRIDE + (kb * 128 + ks * 16) * 2);
#pragma unroll
                for (int nt = 0; nt < 4; ++nt) {
                    uint32_t b0, b1;
                    ldsm_x2(b0, b1, bSlice + nt * 8 * B_STRIDE + ks * 32);
                    mma16816(acc[nt],     a0[0], a1[0], a2[0], a3[0], b0, b1);
                    mma16816(acc[4 + nt], a0[1], a1[1], a2[1], a3[1], b0, b1);
                }
            }
            __syncthreads();
        }

        // ---- chunk epilogue: +b2, online lse, store raw logits ----
        const int cbase = chunk * 128 + cg * 32 + (lane & 3) * 2;
#pragma unroll
        for (int t = 0; t < 2; ++t) {
#pragma unroll
            for (int h = 0; h < 2; ++h) {
                const int idx = t * 2 + h;
                const int row = r0 + rg * 32 + (lane >> 2) + t * 16 + h * 8;
                float x[8];
#pragma unroll
                for (int nt = 0; nt < 4; ++nt) {
                    float2 bv = *(const float2*)&b2s[cbase + nt * 8];
                    x[nt * 2]     = acc[t * 4 + nt][h * 2]     + bv.x;
                    x[nt * 2 + 1] = acc[t * 4 + nt][h * 2 + 1] + bv.y;
                }
                float mx = x[0];
#pragma unroll
                for (int i = 1; i < 8; ++i) mx = fmaxf(mx, x[i]);
                float nm = fmaxf(mr[idx], mx);
                float part = 0.f;
#pragma unroll
                for (int i = 0; i < 8; ++i) part += __expf(x[i] - nm);
                sr[idx] = sr[idx] * __expf(mr[idx] - nm) + part;
                mr[idx] = nm;

                float* orow = out + (size_t)row * CCLS + cbase;
#pragma unroll
                for (int nt = 0; nt < 4; ++nt)
                    *(float2*)(orow + nt * 8) = make_float2(x[nt * 2], x[nt * 2 + 1]);
            }
        }
    }

    // ---- combine lse across the 4 lanes sharing each row, then col groups ----
#pragma unroll
    for (int idx = 0; idx < 4; ++idx) {
        float m = mr[idx], s = sr[idx];
#pragma unroll
        for (int off = 1; off <= 2; off <<= 1) {
            float om = __shfl_xor_sync(0xffffffffu, m, off);
            float os = __shfl_xor_sync(0xffffffffu, s, off);
            float nm = fmaxf(m, om);
            s = s * __expf(m - nm) + os * __expf(om - nm);
            m = nm;
        }
        if ((lane & 3) == 0) {
            const int t = idx >> 1, h = idx & 1;
            const int row = rg * 32 + (lane >> 2) + t * 16 + h * 8;
            scr[row * 4 + cg] = make_float2(m, s);
        }
    }
    __syncthreads();

    if (tid < 128) {
        float m = scr[tid * 4 + 0].x, s = scr[tid * 4 + 0].y;
#pragma unroll
        for (int g = 1; g < 4; ++g) {
            float2 q = scr[tid * 4 + g];
            float nm = fmaxf(m, q.x);
            s = s * __expf(m - nm) + q.y * __expf(q.x - nm);
            m = nm;
        }
        lse[tid] = m + logf(s);
    }
    __syncthreads();

    // ---- fixup: subtract lse over this CTA's 128x1024 block (L2-hot) ----
    for (int idx = tid; idx < 128 * 256; idx += 512) {
        int row = idx >> 8;
        int c4  = (idx & 255) * 4;
        float* p = out + (size_t)(r0 + row) * CCLS + c4;
        float4 v = *(const float4*)p;
        float l = lse[row];
        v.x -= l; v.y -= l; v.z -= l; v.w -= l;
        *(float4*)p = v;
    }
}

// ---------------------------------------------------------------------------
// Launch
// ---------------------------------------------------------------------------
extern "C" void kernel_launch(void* const* d_in, const int* in_sizes, int n_in,
                              void* d_out, int out_size)
{
    const float* enc = (const float*)d_in[0];   // [4,256,512]
    const float* dec = (const float*)d_in[1];   // [4,64,512]
    const float* W1  = (const float*)d_in[2];   // [512,1024]
    const float* b1  = (const float*)d_in[3];   // [512]
    const float* W2  = (const float*)d_in[4];   // [1024,512]
    const float* b2  = (const float*)d_in[5];   // [1024]
    float* out = (float*)d_out;                 // [4,256,64,1024] fp32

    cudaFuncSetAttribute(gemm_joint_kernel,
                         cudaFuncAttributeMaxDynamicSharedMemorySize, GEMM_SMEM);

    w2_to_bf16_kernel<<<2048, 256>>>(W2);
    proj_kernel<<<dim3(16, 8), 256>>>(enc, W1, b1, 1);   // -> g_PE (+b1)
    proj_kernel<<<dim3(4, 8), 256>>>(dec, W1, b1, 0);    // -> g_PD
    h_build_kernel<<<1024, 256>>>();                     // -> g_Hb (bf16)
    gemm_joint_kernel<<<512, 512, GEMM_SMEM>>>(b2, out);
}

// round 14
// speedup vs baseline: 5.4832x; 1.0481x over previous
#include <cuda_runtime.h>
#include <cuda_bf16.h>
#include <math.h>
#include <stdint.h>

// Problem constants
#define DD   512
#define CCLS 1024
#define BB   4
#define MM   256
#define NN   64
#define RR_TOT (BB * MM * NN)   // 65536 rows

// Device-global scratch (allocation-free per harness rules)
__device__ float g_PE[BB * MM * DD];            // [1024][512]  proj_enc + b1
__device__ float g_PD[BB * NN * DD];            // [256][512]   proj_dec
__device__ __nv_bfloat16 g_W2b[CCLS * DD];      // [1024][512]  W2 in bf16 (k-major)
__device__ __nv_bfloat16 g_Hb[(size_t)RR_TOT * DD]; // [65536][512] tanh hidden, bf16

__device__ __forceinline__ uint32_t smem_to_u32(const void* p) {
    uint32_t a;
    asm("{ .reg .u64 t; cvta.to.shared.u64 t, %1; cvt.u32.u64 %0, t; }" : "=r"(a) : "l"(p));
    return a;
}

// ---------------------------------------------------------------------------
// W2 fp32 -> bf16
// ---------------------------------------------------------------------------
__global__ void w2_to_bf16_kernel(const float* __restrict__ W2)
{
    int i = blockIdx.x * 256 + threadIdx.x;   // grid 2048 covers 524288
    g_W2b[i] = __float2bfloat16(W2[i]);
}

// ---------------------------------------------------------------------------
// Projection GEMM (fp32 CUDA cores, small): out[r][k] = (b1) + X[r]·W1[k][off:]
// ---------------------------------------------------------------------------
__global__ __launch_bounds__(256)
void proj_kernel(const float* __restrict__ X, const float* __restrict__ W1,
                 const float* __restrict__ b1, int isEnc)
{
    __shared__ __align__(16) float Xs[16][68];
    __shared__ __align__(16) float Ws[16][68];

    float* outg = isEnc ? g_PE : g_PD;
    const int off = isEnc ? 0 : DD;

    const int r0 = blockIdx.x * 64;
    const int k0 = blockIdx.y * 64;
    const int tid = threadIdx.x;
    const int dd = tid & 15;
    const int rr = tid >> 4;
    const int tx = tid & 15;
    const int ty = tid >> 4;

    float acc[4][4];
#pragma unroll
    for (int i = 0; i < 4; ++i)
#pragma unroll
        for (int j = 0; j < 4; ++j) acc[i][j] = 0.f;

    for (int d0 = 0; d0 < DD; d0 += 16) {
#pragma unroll
        for (int i = 0; i < 4; ++i)
            Xs[dd][rr + 16 * i] = X[(size_t)(r0 + rr + 16 * i) * DD + d0 + dd];
#pragma unroll
        for (int i = 0; i < 4; ++i)
            Ws[dd][rr + 16 * i] = W1[(size_t)(k0 + rr + 16 * i) * (2 * DD) + off + d0 + dd];
        __syncthreads();
#pragma unroll
        for (int d = 0; d < 16; ++d) {
            float4 a  = *(const float4*)&Xs[d][ty * 4];
            float4 bv = *(const float4*)&Ws[d][tx * 4];
            float av[4] = {a.x, a.y, a.z, a.w};
            float bw[4] = {bv.x, bv.y, bv.z, bv.w};
#pragma unroll
            for (int i = 0; i < 4; ++i)
#pragma unroll
                for (int j = 0; j < 4; ++j)
                    acc[i][j] = fmaf(av[i], bw[j], acc[i][j]);
        }
        __syncthreads();
    }
#pragma unroll
    for (int i = 0; i < 4; ++i)
#pragma unroll
        for (int j = 0; j < 4; ++j) {
            float v = acc[i][j];
            if (isEnc) v += b1[k0 + tx * 4 + j];
            outg[(size_t)(r0 + ty * 4 + i) * DD + k0 + tx * 4 + j] = v;
        }
}

// ---------------------------------------------------------------------------
// H build (vectorized): g_Hb[bm*64+n][k] = bf16(tanh(PE[bm][k] + PD[b*64+n][k]))
// ---------------------------------------------------------------------------
__global__ __launch_bounds__(256)
void h_build_kernel()
{
    const int bm = blockIdx.x;
    const int b  = bm >> 8;
    const float* PE = g_PE + (size_t)bm * DD;
    const float* PD = g_PD + (size_t)(b * NN) * DD;
    __nv_bfloat16* H = g_Hb + (size_t)bm * NN * DD;

    for (int i = threadIdx.x; i < NN * (DD / 4); i += 256) {
        int n  = i >> 7;            // 0..63
        int kq = i & 127;           // quad index
        int k  = kq * 4;
        float4 pe = *(const float4*)(PE + k);
        float4 pd = *(const float4*)(PD + (size_t)n * DD + k);
        float t0, t1, t2, t3;
        asm("tanh.approx.f32 %0, %1;" : "=f"(t0) : "f"(pe.x + pd.x));
        asm("tanh.approx.f32 %0, %1;" : "=f"(t1) : "f"(pe.y + pd.y));
        asm("tanh.approx.f32 %0, %1;" : "=f"(t2) : "f"(pe.z + pd.z));
        asm("tanh.approx.f32 %0, %1;" : "=f"(t3) : "f"(pe.w + pd.w));
        __nv_bfloat162 b0 = __floats2bfloat162_rn(t0, t1);
        __nv_bfloat162 b1v = __floats2bfloat162_rn(t2, t3);
        uint2 pack;
        pack.x = *(uint32_t*)&b0;
        pack.y = *(uint32_t*)&b1v;
        *(uint2*)(H + (size_t)n * DD + k) = pack;
    }
}

// ---------------------------------------------------------------------------
// Fused joint GEMM via mma.sync (HMMA bf16) + bias + log-softmax
// Grid 512 x 512 threads (16 warps: 4 rg x 4 cg). CTA: rows [r0, r0+128),
// C=1024 in 4 chunks of 256 cols; warp covers rows [rg*32,+32) x cols
// [cg*64,+64) of the chunk (8 n-tiles). K=512 as 8 slices of 64 per chunk
// (double-buffered B). 32 stages total; 0.1875 KB smem per MMA.
// ---------------------------------------------------------------------------
#define A_STRIDE 1040                  // bytes per A row (520 bf16)
#define B_STRIDE 144                   // bytes per B row (72 bf16; 64k slice)
#define B_SLICE  (256 * B_STRIDE)      // 36864
#define A_OFF    0                     // 128*1040 = 133120
#define B_OFF    133120                // 2 slices = 73728
#define B2_OFF   206848                // 4096
#define SCR_OFF  210944                // float2[128][4] = 4096
#define LSE_OFF  215040                // 512
#define GEMM_SMEM 215552

__device__ __forceinline__ void ldsm_x4(uint32_t& a0, uint32_t& a1, uint32_t& a2, uint32_t& a3,
                                        uint32_t addr) {
    asm volatile("ldmatrix.sync.aligned.m8n8.x4.shared.b16 {%0,%1,%2,%3}, [%4];"
                 : "=r"(a0), "=r"(a1), "=r"(a2), "=r"(a3) : "r"(addr));
}
__device__ __forceinline__ void ldsm_x2(uint32_t& b0, uint32_t& b1, uint32_t addr) {
    asm volatile("ldmatrix.sync.aligned.m8n8.x2.shared.b16 {%0,%1}, [%2];"
                 : "=r"(b0), "=r"(b1) : "r"(addr));
}
__device__ __forceinline__ void mma16816(float* d, uint32_t a0, uint32_t a1, uint32_t a2,
                                         uint32_t a3, uint32_t b0, uint32_t b1) {
    asm volatile("mma.sync.aligned.m16n8k16.row.col.f32.bf16.bf16.f32 "
                 "{%0,%1,%2,%3}, {%4,%5,%6,%7}, {%8,%9}, {%0,%1,%2,%3};"
                 : "+f"(d[0]), "+f"(d[1]), "+f"(d[2]), "+f"(d[3])
                 : "r"(a0), "r"(a1), "r"(a2), "r"(a3), "r"(b0), "r"(b1));
}

__global__ __launch_bounds__(512, 1)
void gemm_joint_kernel(const float* __restrict__ b2, float* __restrict__ out)
{
    extern __shared__ __align__(16) char smem[];
    const uint32_t sb = smem_to_u32(smem);
    const int tid  = threadIdx.x;
    const int wid  = tid >> 5;
    const int lane = tid & 31;
    const int rg   = wid >> 2;            // row group 0..3
    const int cg   = wid & 3;             // col group 0..3 (64 cols each)
    const int r0   = blockIdx.x * 128;

    float* b2s = (float*)(smem + B2_OFF);
    float2* scr = (float2*)(smem + SCR_OFF);   // [row][colg 0..3]
    float* lse = (float*)(smem + LSE_OFF);

    // b2 -> smem
    for (int i = tid; i < CCLS; i += 512) b2s[i] = b2[i];

    // Stage A tile: 128 rows x 512 bf16, padded stride
    {
        const __nv_bfloat16* Hbase = g_Hb + (size_t)r0 * DD;
        for (int idx = tid; idx < 128 * 64; idx += 512) {
            int row = idx >> 6;
            int kc  = idx & 63;
            uint4 v = *(const uint4*)(Hbase + (size_t)row * DD + kc * 8);
            *(uint4*)(smem + A_OFF + row * A_STRIDE + kc * 16) = v;
        }
    }

    // ldmatrix lane addresses
    const uint32_t aLane = sb + A_OFF + (rg * 32 + (lane & 15)) * A_STRIDE + (lane >> 4) * 16;
    const uint32_t bLaneBase = sb + B_OFF +
        (cg * 64 + (lane & 7)) * B_STRIDE + ((lane >> 3) & 1) * 16;

    // B prefetch: thread loads 4 uint4 per 256-row x 64-k slice (32KB / 512 thr)
    const int pn = tid >> 3;        // 0..63  (rows pn + j*64)
    const int pk = tid & 7;         // 16B chunk within 128B slice row
    uint4 pb[4];
#pragma unroll
    for (int j = 0; j < 4; ++j)
        pb[j] = *(const uint4*)(g_W2b + (size_t)(pn + j * 64) * DD + pk * 8);  // chunk0,slice0

    float mr[4], sr[4];
#pragma unroll
    for (int i = 0; i < 4; ++i) { mr[i] = -INFINITY; sr[i] = 0.f; }

    for (int chunk = 0; chunk < 4; ++chunk) {
        float acc[16][4];                 // [t*8+nt][4]
#pragma unroll
        for (int i = 0; i < 16; ++i)
#pragma unroll
            for (int j = 0; j < 4; ++j) acc[i][j] = 0.f;

        for (int kb = 0; kb < 8; ++kb) {
            const int stage = chunk * 8 + kb;
            const int buf = stage & 1;
            // store prefetched slice
            char* bd = smem + B_OFF + buf * B_SLICE;
#pragma unroll
            for (int j = 0; j < 4; ++j)
                *(uint4*)(bd + (pn + j * 64) * B_STRIDE + pk * 16) = pb[j];
            __syncthreads();

            // prefetch next slice
            if (stage < 31) {
                const int ns = stage + 1;
                const int nc = ns >> 3, nkb = ns & 7;
                const __nv_bfloat16* src =
                    g_W2b + (size_t)(nc * 256 + pn) * DD + nkb * 64 + pk * 8;
#pragma unroll
                for (int j = 0; j < 4; ++j)
                    pb[j] = *(const uint4*)(src + (size_t)j * 64 * DD);
            }

            // compute: 4 k-steps of 16 over this 64-k slice
            const uint32_t bSlice = bLaneBase + buf * B_SLICE;
#pragma unroll
            for (int ks = 0; ks < 4; ++ks) {
                uint32_t a0[2], a1[2], a2[2], a3[2];
#pragma unroll
                for (int t = 0; t < 2; ++t)
                    ldsm_x4(a0[t], a1[t], a2[t], a3[t],
                            aLane + t * 16 * A_STRIDE + (kb * 64 + ks * 16) * 2);
#pragma unroll
                for (int nt = 0; nt < 8; ++nt) {
                    uint32_t b0, b1;
                    ldsm_x2(b0, b1, bSlice + nt * 8 * B_STRIDE + ks * 32);
                    mma16816(acc[nt],     a0[0], a1[0], a2[0], a3[0], b0, b1);
                    mma16816(acc[8 + nt], a0[1], a1[1], a2[1], a3[1], b0, b1);
                }
            }
            __syncthreads();
        }

        // ---- chunk epilogue: +b2, online lse, store raw logits ----
        const int cbase = chunk * 256 + cg * 64 + (lane & 3) * 2;
#pragma unroll
        for (int t = 0; t < 2; ++t) {
#pragma unroll
            for (int h = 0; h < 2; ++h) {
                const int idx = t * 2 + h;
                const int row = r0 + rg * 32 + (lane >> 2) + t * 16 + h * 8;
                float x[16];
#pragma unroll
                for (int nt = 0; nt < 8; ++nt) {
                    float2 bv = *(const float2*)&b2s[cbase + nt * 8];
                    x[nt * 2]     = acc[t * 8 + nt][h * 2]     + bv.x;
                    x[nt * 2 + 1] = acc[t * 8 + nt][h * 2 + 1] + bv.y;
                }
                float mx = x[0];
#pragma unroll
                for (int i = 1; i < 16; ++i) mx = fmaxf(mx, x[i]);
                float nm = fmaxf(mr[idx], mx);
                float part = 0.f;
#pragma unroll
                for (int i = 0; i < 16; ++i) part += __expf(x[i] - nm);
                sr[idx] = sr[idx] * __expf(mr[idx] - nm) + part;
                mr[idx] = nm;

                float* orow = out + (size_t)row * CCLS + cbase;
#pragma unroll
                for (int nt = 0; nt < 8; ++nt)
                    *(float2*)(orow + nt * 8) = make_float2(x[nt * 2], x[nt * 2 + 1]);
            }
        }
    }

    // ---- combine lse across the 4 lanes sharing each row, then col groups ----
#pragma unroll
    for (int idx = 0; idx < 4; ++idx) {
        float m = mr[idx], s = sr[idx];
#pragma unroll
        for (int off = 1; off <= 2; off <<= 1) {
            float om = __shfl_xor_sync(0xffffffffu, m, off);
            float os = __shfl_xor_sync(0xffffffffu, s, off);
            float nm = fmaxf(m, om);
            s = s * __expf(m - nm) + os * __expf(om - nm);
            m = nm;
        }
        if ((lane & 3) == 0) {
            const int t = idx >> 1, h = idx & 1;
            const int row = rg * 32 + (lane >> 2) + t * 16 + h * 8;
            scr[row * 4 + cg] = make_float2(m, s);
        }
    }
    __syncthreads();

    if (tid < 128) {
        float m = scr[tid * 4 + 0].x, s = scr[tid * 4 + 0].y;
#pragma unroll
        for (int g = 1; g < 4; ++g) {
            float2 q = scr[tid * 4 + g];
            float nm = fmaxf(m, q.x);
            s = s * __expf(m - nm) + q.y * __expf(q.x - nm);
            m = nm;
        }
        lse[tid] = m + logf(s);
    }
    __syncthreads();

    // ---- fixup: subtract lse over this CTA's 128x1024 block (L2-hot) ----
    for (int idx = tid; idx < 128 * 256; idx += 512) {
        int row = idx >> 8;
        int c4  = (idx & 255) * 4;
        float* p = out + (size_t)(r0 + row) * CCLS + c4;
        float4 v = *(const float4*)p;
        float l = lse[row];
        v.x -= l; v.y -= l; v.z -= l; v.w -= l;
        *(float4*)p = v;
    }
}

// ---------------------------------------------------------------------------
// Launch
// ---------------------------------------------------------------------------
extern "C" void kernel_launch(void* const* d_in, const int* in_sizes, int n_in,
                              void* d_out, int out_size)
{
    const float* enc = (const float*)d_in[0];   // [4,256,512]
    const float* dec = (const float*)d_in[1];   // [4,64,512]
    const float* W1  = (const float*)d_in[2];   // [512,1024]
    const float* b1  = (const float*)d_in[3];   // [512]
    const float* W2  = (const float*)d_in[4];   // [1024,512]
    const float* b2  = (const float*)d_in[5];   // [1024]
    float* out = (float*)d_out;                 // [4,256,64,1024] fp32

    cudaFuncSetAttribute(gemm_joint_kernel,
                         cudaFuncAttributeMaxDynamicSharedMemorySize, GEMM_SMEM);

    w2_to_bf16_kernel<<<2048, 256>>>(W2);
    proj_kernel<<<dim3(16, 8), 256>>>(enc, W1, b1, 1);   // -> g_PE (+b1)
    proj_kernel<<<dim3(4, 8), 256>>>(dec, W1, b1, 0);    // -> g_PD
    h_build_kernel<<<1024, 256>>>();                     // -> g_Hb (bf16)
    gemm_joint_kernel<<<512, 512, GEMM_SMEM>>>(b2, out);
}